// round 13
// baseline (speedup 1.0000x reference)
#include <cuda_runtime.h>
#include <cuda_fp16.h>
#include <cstdint>

#define B_    8
#define V_    4096
#define P_    32
#define CIN   64
#define COUT  128
#define BV    (B_ * V_)      // 32768
#define K2    512

__device__ __half g_ypow[(size_t)BV * K2];
__device__ __half g_W[(size_t)COUT * K2];
__device__ __half g_S16[(size_t)B_ * V_ * CIN];

__device__ __forceinline__ void mma_f16(float& d0, float& d1, float& d2, float& d3,
                                        uint32_t a0, uint32_t a1, uint32_t a2, uint32_t a3,
                                        uint32_t b0, uint32_t b1) {
    asm volatile(
        "mma.sync.aligned.m16n8k16.row.col.f32.f16.f16.f32 "
        "{%0,%1,%2,%3}, {%4,%5,%6,%7}, {%8,%9}, {%0,%1,%2,%3};"
        : "+f"(d0), "+f"(d1), "+f"(d2), "+f"(d3)
        : "r"(a0), "r"(a1), "r"(a2), "r"(a3), "r"(b0), "r"(b1));
}

__device__ __forceinline__ void ldsm_x4(uint32_t* r, uint32_t addr) {
    asm volatile("ldmatrix.sync.aligned.m8n8.x4.shared.b16 {%0,%1,%2,%3}, [%4];"
        : "=r"(r[0]), "=r"(r[1]), "=r"(r[2]), "=r"(r[3]) : "r"(addr));
}

__device__ __forceinline__ void ldsm_x4_t(uint32_t* r, uint32_t addr) {
    asm volatile("ldmatrix.sync.aligned.m8n8.x4.trans.shared.b16 {%0,%1,%2,%3}, [%4];"
        : "=r"(r[0]), "=r"(r[1]), "=r"(r[2]), "=r"(r[3]) : "r"(addr));
}

__device__ __forceinline__ float sqclip(float x) {
    return sqrtf(fmaxf(x, 1e-4f));
}

__device__ __forceinline__ uint32_t smem_u32(const void* p) {
    return (uint32_t)__cvta_generic_to_shared(p);
}

__device__ __forceinline__ void cp_async16(uint32_t dst, const void* src) {
    asm volatile("cp.async.cg.shared.global [%0], [%1], 16;" :: "r"(dst), "l"(src));
}

// XOR swizzle, 16-word (64B) rows, chunk c in 0..3
__device__ __forceinline__ int swz(int row, int c) {
    return row * 16 + ((c ^ ((row >> 1) & 3)) << 2);
}
// XOR swizzle, 32-word (128B) rows, chunk c in 0..7
__device__ __forceinline__ int swz8(int row, int c) {
    return row * 32 + ((c ^ (row & 7)) << 2);
}

__device__ __forceinline__ uint4 pack8h(float4 v0, float4 v1) {
    __half2 h0 = __floats2half2_rn(v0.x, v0.y);
    __half2 h1 = __floats2half2_rn(v0.z, v0.w);
    __half2 h2 = __floats2half2_rn(v1.x, v1.y);
    __half2 h3 = __floats2half2_rn(v1.z, v1.w);
    uint4 u;
    u.x = *(uint32_t*)&h0; u.y = *(uint32_t*)&h1;
    u.z = *(uint32_t*)&h2; u.w = *(uint32_t*)&h3;
    return u;
}

// ---------------------------------------------------------------------------
// Prologue: signal (CTAs 0..1023) and W (CTAs 1024..1055) fp32 -> fp16.
// 2 float4 per thread.
// ---------------------------------------------------------------------------
__global__ __launch_bounds__(256)
void cvt_kernel(const float* __restrict__ signal, const float* __restrict__ W)
{
    const int cta = blockIdx.x;
    const float4* src;
    uint2* dst;
    int base;
    if (cta < 1024) {
        src = (const float4*)signal;  dst = (uint2*)g_S16;
        base = cta * 512 + threadIdx.x;
    } else {
        src = (const float4*)W;       dst = (uint2*)g_W;
        base = (cta - 1024) * 512 + threadIdx.x;
    }
    #pragma unroll
    for (int j = 0; j < 2; ++j) {
        int i = base + j * 256;
        float4 v = src[i];
        __half2 h0 = __floats2half2_rn(v.x, v.y);
        __half2 h1 = __floats2half2_rn(v.z, v.w);
        uint2 u;
        u.x = *(uint32_t*)&h0; u.y = *(uint32_t*)&h1;
        dst[i] = u;
    }
}

// ---------------------------------------------------------------------------
// Kernel 1: persistent pipelined.  CTA = 64 threads = 2 warps, processes
// NBV consecutive bv.  While bv i computes, bv i+1's ck (raw fp32) and
// gathered S (fp16) stream in via cp.async double buffers; ck converts to
// the fp16 swizzled tile in a short smem pass after the hidden wait.
// mma/bounce/epilogue identical to R12.
// ---------------------------------------------------------------------------
#define NBV    8
#define YB_STR 36   // bounce row stride in words (half2 units)

__global__ __launch_bounds__(64, 10)
void ypow_kernel(const int*   __restrict__ pidx,
                 const float* __restrict__ convk)
{
    __shared__ uint32_t sCKr[1024];          // ck raw fp32 (4KB)
    __shared__ uint32_t sCK16[2][512];       // fp16 swizzled ck tiles
    __shared__ uint32_t sS[2][2][512];       // [stage][warp] S halves
    __shared__ uint32_t sBn[2][576];         // per-warp bounce

    const int tid  = threadIdx.x;
    const int warp = tid >> 5;
    const int lane = tid & 31;
    const int bv0  = blockIdx.x * NBV;
    const int g    = lane >> 2;
    const int tig  = lane & 3;
    const int grp  = lane >> 3;
    const int gi   = lane & 7;
    const int2* pidx2 = (const int2*)pidx;

    auto prefetch = [&](int bv, int st) {
        // S gather for this warp's c-half
        const int2 ip = pidx2[bv * P_ + lane];
        const int base = (ip.x * V_ + ip.y) * CIN;
        uint32_t* s = sS[st][warp];
        #pragma unroll
        for (int j = 0; j < 4; ++j) {
            int id = j * 32 + lane;
            int row = id >> 2, c = id & 3;
            int bp = __shfl_sync(0xffffffffu, base, row);
            cp_async16(smem_u32(&s[swz(row, c)]), g_S16 + bp + warp * 32 + c * 8);
        }
        // ck raw fp32: 256 chunks, 4 per thread, linear
        const float* ck = convk + (size_t)bv * 1024;
        #pragma unroll
        for (int it = 0; it < 4; ++it) {
            int id = tid + it * 64;
            cp_async16(smem_u32(&sCKr[id * 4]), ck + id * 4);
        }
        asm volatile("cp.async.commit_group;");
    };

    auto convert = [&](int st) {
        #pragma unroll
        for (int it = 0; it < 2; ++it) {
            int id = tid + it * 64;
            int row = id >> 2, c = id & 3;
            const float4* p = (const float4*)&sCKr[row * 32 + c * 8];
            *(uint4*)&sCK16[st][swz(row, c)] = pack8h(p[0], p[1]);
        }
    };

    // prologue: land bv0, convert its ck
    prefetch(bv0, 0);
    asm volatile("cp.async.wait_group 0;");
    __syncthreads();
    convert(0);
    __syncthreads();

    for (int i = 0; i < NBV; ++i) {
        const int cur = i & 1;
        const int bv  = bv0 + i;

        if (i + 1 < NBV) prefetch(bv + 1, cur ^ 1);

        const uint32_t sCKb = smem_u32(sCK16[cur]);
        const uint32_t sSb  = smem_u32(sS[cur][warp]);

        float acc[2][4][4];
        #pragma unroll
        for (int x = 0; x < 2; ++x)
            #pragma unroll
            for (int y = 0; y < 4; ++y)
                #pragma unroll
                for (int e = 0; e < 4; ++e) acc[x][y][e] = 0.0f;

        #pragma unroll
        for (int ks = 0; ks < 2; ++ks) {
            uint32_t a[2][4];
            #pragma unroll
            for (int mt = 0; mt < 2; ++mt) {
                int row = ks * 16 + (grp >> 1) * 8 + gi;
                int ch  = mt * 2 + (grp & 1);
                ldsm_x4_t(a[mt], sCKb + 4 * swz(row, ch));
            }
            uint32_t b[2][4];
            #pragma unroll
            for (int ntp = 0; ntp < 2; ++ntp) {
                int row = ks * 16 + (grp & 1) * 8 + gi;
                int ch  = ntp * 2 + (grp >> 1);
                ldsm_x4_t(b[ntp], sSb + 4 * swz(row, ch));
            }
            #pragma unroll
            for (int mt = 0; mt < 2; ++mt)
                #pragma unroll
                for (int nt = 0; nt < 4; ++nt) {
                    uint32_t b0 = b[nt >> 1][(nt & 1) * 2];
                    uint32_t b1 = b[nt >> 1][(nt & 1) * 2 + 1];
                    mma_f16(acc[mt][nt][0], acc[mt][nt][1], acc[mt][nt][2], acc[mt][nt][3],
                            a[mt][0], a[mt][1], a[mt][2], a[mt][3], b0, b1);
                }
        }

        // bounce [c2][rn] half2, stride 36
        uint32_t* sY = sBn[warp];
        #pragma unroll
        for (int mt = 0; mt < 2; ++mt) {
            #pragma unroll
            for (int nt = 0; nt < 4; ++nt) {
                const int c2 = nt * 4 + tig;
                const int rn = mt * 16 + g;
                __half2 h01 = __floats2half2_rn(acc[mt][nt][0], acc[mt][nt][1]);
                __half2 h23 = __floats2half2_rn(acc[mt][nt][2], acc[mt][nt][3]);
                sY[c2 * YB_STR + rn]     = *(uint32_t*)&h01;
                sY[c2 * YB_STR + rn + 8] = *(uint32_t*)&h23;
            }
        }
        __syncwarp();

        // epilogue: lane = (c2, r-half); incremental l-bucket accumulate
        {
            const uint32_t* rp = sY + (lane & 15) * YB_STR + (lane >> 4) * 16;
            float s0[4] = {0.f, 0.f, 0.f, 0.f};
            float s1[4] = {0.f, 0.f, 0.f, 0.f};
            #pragma unroll
            for (int j = 0; j < 4; ++j) {
                uint4 q = *(const uint4*)&rp[j * 4];
                uint32_t w[4] = {q.x, q.y, q.z, q.w};
                #pragma unroll
                for (int e = 0; e < 4; ++e) {
                    const int n = j * 4 + e;
                    const int l = (n == 0) ? 0 : (n <= 3) ? 1 : (n <= 8) ? 2 : 3;
                    float2 f = __half22float2(*(const __half2*)&w[e]);
                    s0[l] += f.x * f.x;
                    s1[l] += f.y * f.y;
                }
            }
            __half2 u0 = __floats2half2_rn(sqclip(s0[0]), sqclip(s0[1]));
            __half2 u1 = __floats2half2_rn(sqclip(s0[2]), sqclip(s0[3]));
            __half2 u2 = __floats2half2_rn(sqclip(s1[0]), sqclip(s1[1]));
            __half2 u3 = __floats2half2_rn(sqclip(s1[2]), sqclip(s1[3]));
            uint32_t w0 = *(uint32_t*)&u0, w1 = *(uint32_t*)&u1;
            uint32_t w2 = *(uint32_t*)&u2, w3 = *(uint32_t*)&u3;
            uint32_t p0 = __shfl_xor_sync(0xffffffffu, w0, 16);
            uint32_t p1 = __shfl_xor_sync(0xffffffffu, w1, 16);
            uint32_t p2 = __shfl_xor_sync(0xffffffffu, w2, 16);
            uint32_t p3 = __shfl_xor_sync(0xffffffffu, w3, 16);
            uint4 o;
            int c;
            if (lane < 16) {
                c = 2 * (lane & 15);
                o.x = w0; o.y = w1; o.z = p0; o.w = p1;
            } else {
                c = 2 * (lane & 15) + 1;
                o.x = p2; o.y = p3; o.z = w2; o.w = w3;
            }
            ((uint4*)g_ypow)[(size_t)bv * 64 + warp * 32 + c] = o;
        }
        __syncwarp();   // bounce reads done before next iter's writes

        if (i + 1 < NBV) {
            asm volatile("cp.async.wait_group 0;");
            __syncthreads();            // next-stage data visible to all
            convert(cur ^ 1);           // ck raw -> fp16 tile for i+1
            __syncthreads();
        }
    }
}

// ---------------------------------------------------------------------------
// Kernel 2: out = ypow * W^T + bias, relu.  fp16 m16n8k16 mma.  CTA 256 thr,
// tile 128m x 128n, KT=64 halves, 3-stage cp.async pipeline (8 iterations),
// 128B-row XOR swizzle, ldmatrix.x4 frags.  Warp = 32m x 64n.
// ---------------------------------------------------------------------------
#define KT     64
#define NKT    (K2 / KT)        // 8
#define M_BLK  128
#define N_BLK  128

__global__ __launch_bounds__(256, 2)
void out_gemm_kernel(const float* __restrict__ bias,
                     float* __restrict__ out)
{
    __shared__ uint32_t sA[3][M_BLK * 32];   // 3 x 16KB
    __shared__ uint32_t sB[3][N_BLK * 32];   // 3 x 16KB

    const int tid  = threadIdx.x;
    const int warp = tid >> 5;
    const int lane = tid & 31;
    const int g    = lane >> 2;
    const int tig  = lane & 3;
    const int wm   = warp >> 1;
    const int wn   = warp & 1;
    const int m0   = blockIdx.x * M_BLK;
    const int lrow = lane & 15;
    const int lch  = lane >> 4;

    const __half* yp = g_ypow;

    float acc[2][8][4];
    #pragma unroll
    for (int a = 0; a < 2; ++a)
        #pragma unroll
        for (int b = 0; b < 8; ++b)
            #pragma unroll
            for (int c = 0; c < 4; ++c) acc[a][b][c] = 0.0f;

    auto stage = [&](int kt, int st) {
        #pragma unroll
        for (int i = 0; i < 4; ++i) {          // A: 1024 chunks
            int id = tid + i * 256;
            int row = id >> 3, c = id & 7;
            cp_async16(smem_u32(&sA[st][swz8(row, c)]),
                       yp + (size_t)(m0 + row) * K2 + kt * KT + c * 8);
        }
        #pragma unroll
        for (int i = 0; i < 4; ++i) {          // B: 1024 chunks
            int id = tid + i * 256;
            int row = id >> 3, c = id & 7;
            cp_async16(smem_u32(&sB[st][swz8(row, c)]),
                       g_W + (size_t)row * K2 + kt * KT + c * 8);
        }
        asm volatile("cp.async.commit_group;");
    };

    stage(0, 0);
    stage(1, 1);
    stage(2, 2);

    for (int kt = 0; kt < NKT; ++kt) {
        if (kt < NKT - 2)      asm volatile("cp.async.wait_group 2;");
        else if (kt == NKT - 2) asm volatile("cp.async.wait_group 1;");
        else                    asm volatile("cp.async.wait_group 0;");
        __syncthreads();
        const int st = kt % 3;

        #pragma unroll
        for (int ks = 0; ks < 4; ++ks) {
            const int ch = ks * 2 + lch;
            uint32_t a[2][4];
            #pragma unroll
            for (int mi = 0; mi < 2; ++mi) {
                int row = wm * 32 + mi * 16 + lrow;
                ldsm_x4(a[mi], smem_u32(&sA[st][swz8(row, ch)]));
            }
            uint32_t b[4][4];
            #pragma unroll
            for (int p = 0; p < 4; ++p) {
                int row = wn * 64 + p * 16 + lrow;
                ldsm_x4(b[p], smem_u32(&sB[st][swz8(row, ch)]));
            }
            #pragma unroll
            for (int p = 0; p < 4; ++p) {
                mma_f16(acc[0][2*p][0], acc[0][2*p][1], acc[0][2*p][2], acc[0][2*p][3],
                        a[0][0], a[0][1], a[0][2], a[0][3], b[p][0], b[p][2]);
                mma_f16(acc[0][2*p+1][0], acc[0][2*p+1][1], acc[0][2*p+1][2], acc[0][2*p+1][3],
                        a[0][0], a[0][1], a[0][2], a[0][3], b[p][1], b[p][3]);
                mma_f16(acc[1][2*p][0], acc[1][2*p][1], acc[1][2*p][2], acc[1][2*p][3],
                        a[1][0], a[1][1], a[1][2], a[1][3], b[p][0], b[p][2]);
                mma_f16(acc[1][2*p+1][0], acc[1][2*p+1][1], acc[1][2*p+1][2], acc[1][2*p+1][3],
                        a[1][0], a[1][1], a[1][2], a[1][3], b[p][1], b[p][3]);
            }
        }
        __syncthreads();                      // buffer st free
        if (kt + 3 < NKT) stage(kt + 3, st);  // refill into just-freed buffer
    }

    #pragma unroll
    for (int nt = 0; nt < 8; ++nt) {
        const int col = wn * 64 + nt * 8 + 2 * tig;
        const float b0 = __ldg(&bias[col]);
        const float b1 = __ldg(&bias[col + 1]);
        #pragma unroll
        for (int mi = 0; mi < 2; ++mi) {
            const int row = m0 + wm * 32 + mi * 16 + g;
            float2 v0, v1;
            v0.x = fmaxf(acc[mi][nt][0] + b0, 0.0f);
            v0.y = fmaxf(acc[mi][nt][1] + b1, 0.0f);
            v1.x = fmaxf(acc[mi][nt][2] + b0, 0.0f);
            v1.y = fmaxf(acc[mi][nt][3] + b1, 0.0f);
            *(float2*)(out + (size_t)row * COUT + col)       = v0;
            *(float2*)(out + (size_t)(row + 8) * COUT + col) = v1;
        }
    }
}

extern "C" void kernel_launch(void* const* d_in, const int* in_sizes, int n_in,
                              void* d_out, int out_size)
{
    const float* signal = (const float*)d_in[0];
    const int*   pidx   = (const int*)  d_in[1];
    const float* convk  = (const float*)d_in[2];
    const float* W      = (const float*)d_in[3];
    const float* bias   = (const float*)d_in[4];
    float* out = (float*)d_out;

    cvt_kernel<<<1056, 256>>>(signal, W);
    ypow_kernel<<<BV / NBV, 64>>>(pidx, convk);
    out_gemm_kernel<<<BV / M_BLK, 256>>>(bias, out);
}